// round 15
// baseline (speedup 1.0000x reference)
#include <cuda_runtime.h>
#include <cuda_bf16.h>
#include <cstdint>

#define Nn 50000
#define Ee 1600000
#define Hh 64
#define INC 7
#define ED 4
#define Gg 256
#define FCH 128
#define NC 2
#define CH 64                      // edges per 16-lane group (Ee % CH == 0)
#define SB 196                     // scan blocks (SB*256 >= Nn)
#define FB 782                     // fused scatter+proj blocks (FB*256*8 == Ee)

// ---------------- device scratch ----------------------------------------------------
__device__ __align__(16) float g_xl[Nn * Hh];
__device__ __align__(16) float g_xr[Nn * Hh];
__device__ __align__(16) float g_agg[Nn * Hh];
__device__ float g_den[Nn];
__device__ float g_pool[Gg * Hh];
__device__ float g_cnt[Gg];
__device__ int   g_cur[Nn];                    // zero-init; re-zeroed by head_kernel
__device__ int   g_off[Nn + 1];
__device__ int   g_bsum[SB];
__device__ __align__(16) int    g_rank[Ee];          // per-edge rank within dst bucket
__device__ __align__(16) int    g_sd[2 * Ee + 16];   // (src,dst) pairs, dst-sorted (+pad)
__device__ __align__(16) float4 g_eaS[Ee];           // edge_attr permuted to sorted order

// ---------------- histogram + rank capture (8 edges/thread) ------------------------
__global__ void hist_kernel(const int* __restrict__ ei) {
    int i = (blockIdx.x * 256 + threadIdx.x) * 8;
    if (i >= Ee) return;
    int4 da = *reinterpret_cast<const int4*>(ei + Ee + i);
    int4 db = *reinterpret_cast<const int4*>(ei + Ee + i + 4);
    int4 ra, rb;
    ra.x = atomicAdd(&g_cur[da.x], 1);
    ra.y = atomicAdd(&g_cur[da.y], 1);
    ra.z = atomicAdd(&g_cur[da.z], 1);
    ra.w = atomicAdd(&g_cur[da.w], 1);
    rb.x = atomicAdd(&g_cur[db.x], 1);
    rb.y = atomicAdd(&g_cur[db.y], 1);
    rb.z = atomicAdd(&g_cur[db.z], 1);
    rb.w = atomicAdd(&g_cur[db.w], 1);
    *reinterpret_cast<int4*>(g_rank + i) = ra;
    *reinterpret_cast<int4*>(g_rank + i + 4) = rb;
}

// ---------------- parallel scan stages ---------------------------------------------
__global__ __launch_bounds__(256) void scanA_kernel() {
    __shared__ int sp[256];
    int t = threadIdx.x;
    int i = blockIdx.x * 256 + t;
    int v = (i < Nn) ? g_cur[i] : 0;
    sp[t] = v;
    __syncthreads();
#pragma unroll
    for (int off = 128; off > 0; off >>= 1) {
        if (t < off) sp[t] += sp[t + off];
        __syncthreads();
    }
    if (t == 0) g_bsum[blockIdx.x] = sp[0];
}

__global__ __launch_bounds__(256) void scanB_kernel() {
    __shared__ int sp[256];
    int t = threadIdx.x;
    int v = (t < SB) ? g_bsum[t] : 0;
    sp[t] = v;
    __syncthreads();
#pragma unroll
    for (int off = 1; off < 256; off <<= 1) {
        int u = (t >= off) ? sp[t - off] : 0;
        __syncthreads();
        sp[t] += u;
        __syncthreads();
    }
    if (t < SB) g_bsum[t] = sp[t] - v;   // exclusive
    for (int i = t; i < Gg * Hh; i += 256) g_pool[i] = 0.0f;
    if (t < Gg) g_cnt[t] = 0.0f;
}

__global__ __launch_bounds__(256) void scanC_kernel() {
    __shared__ int sp[256];
    int t = threadIdx.x;
    int i = blockIdx.x * 256 + t;
    int v = (i < Nn) ? g_cur[i] : 0;
    sp[t] = v;
    __syncthreads();
#pragma unroll
    for (int off = 1; off < 256; off <<= 1) {
        int u = (t >= off) ? sp[t - off] : 0;
        __syncthreads();
        sp[t] += u;
        __syncthreads();
    }
    if (i < Nn) g_off[i] = g_bsum[blockIdx.x] + sp[t] - v;   // exclusive prefix
    if (i == Nn - 1) g_off[Nn] = Ee;
}

// ---------------- fused: atomic-free scatter (8 edges/thread) + proj0 --------------
// scatter is latency-bound with idle issue slots; proj0's FMAs fill them.
// stride FB*256 is divisible by 64 -> each thread's h is constant -> W in registers.
__global__ __launch_bounds__(256) void scatproj_kernel(const int* __restrict__ ei,
                                                       const float* __restrict__ ea,
                                                       const float* __restrict__ x,
                                                       const float* __restrict__ Wl,
                                                       const float* __restrict__ bl,
                                                       const float* __restrict__ Wr,
                                                       const float* __restrict__ br) {
    int t = threadIdx.x;
    // ---- scatter phase (8 edges) ----
    {
        int i = (blockIdx.x * 256 + t) * 8;
        if (i < Ee) {
            int4 sa = *reinterpret_cast<const int4*>(ei + i);
            int4 sb = *reinterpret_cast<const int4*>(ei + i + 4);
            int4 da = *reinterpret_cast<const int4*>(ei + Ee + i);
            int4 db = *reinterpret_cast<const int4*>(ei + Ee + i + 4);
            int4 ra = *reinterpret_cast<const int4*>(g_rank + i);
            int4 rb = *reinterpret_cast<const int4*>(g_rank + i + 4);
            int ss[8] = {sa.x, sa.y, sa.z, sa.w, sb.x, sb.y, sb.z, sb.w};
            int dd[8] = {da.x, da.y, da.z, da.w, db.x, db.y, db.z, db.w};
            int rr[8] = {ra.x, ra.y, ra.z, ra.w, rb.x, rb.y, rb.z, rb.w};
            float4 ev[8];
#pragma unroll
            for (int k = 0; k < 8; k++) ev[k] = *reinterpret_cast<const float4*>(ea + 4 * (i + k));
            int pp[8];
#pragma unroll
            for (int k = 0; k < 8; k++) pp[k] = g_off[dd[k]] + rr[k];
#pragma unroll
            for (int k = 0; k < 8; k++) {
                *reinterpret_cast<int2*>(g_sd + 2 * pp[k]) = make_int2(ss[k], dd[k]);
                g_eaS[pp[k]] = ev[k];
            }
        }
    }
    // ---- proj0 phase (grid-stride; h constant per thread) ----
    int h = t & 63;
    float wl[INC], wr[INC];
#pragma unroll
    for (int k = 0; k < INC; k++) {
        wl[k] = Wl[k * Hh + h];
        wr[k] = Wr[k * Hh + h];
    }
    float blv = bl[h];
    float brv = br[h];
    const int stride = FB * 256;   // divisible by 64
#pragma unroll 1
    for (int idx = blockIdx.x * 256 + t; idx < Nn * Hh; idx += stride) {
        int n = idx >> 6;
        const float* xrow = x + n * INC;
        float al = blv;
        float ar = brv;
#pragma unroll
        for (int k = 0; k < INC; k++) {
            float xv = xrow[k];
            al = fmaf(xv, wl[k], al);
            ar = fmaf(xv, wr[k], ar);
        }
        g_xl[idx] = al;
        g_xr[idx] = ar;
        g_agg[idx] = 0.0f;
        if (h == 0) g_den[n] = 0.0f;
    }
}

// ---------------- per-edge score helper --------------------------------------------
__device__ __forceinline__ float sc4(float4 xl, float4 xr, float4 ea,
                                     const float* at, const float (*wk)[4]) {
    float p = 0.0f, v;
    v = xl.x + xr.x;
    v = fmaf(ea.x, wk[0][0], v); v = fmaf(ea.y, wk[0][1], v);
    v = fmaf(ea.z, wk[0][2], v); v = fmaf(ea.w, wk[0][3], v);
    v = v > 0.0f ? v : 0.2f * v; p = fmaf(v, at[0], p);
    v = xl.y + xr.y;
    v = fmaf(ea.x, wk[1][0], v); v = fmaf(ea.y, wk[1][1], v);
    v = fmaf(ea.z, wk[1][2], v); v = fmaf(ea.w, wk[1][3], v);
    v = v > 0.0f ? v : 0.2f * v; p = fmaf(v, at[1], p);
    v = xl.z + xr.z;
    v = fmaf(ea.x, wk[2][0], v); v = fmaf(ea.y, wk[2][1], v);
    v = fmaf(ea.z, wk[2][2], v); v = fmaf(ea.w, wk[2][3], v);
    v = v > 0.0f ? v : 0.2f * v; p = fmaf(v, at[2], p);
    v = xl.w + xr.w;
    v = fmaf(ea.x, wk[3][0], v); v = fmaf(ea.y, wk[3][1], v);
    v = fmaf(ea.z, wk[3][2], v); v = fmaf(ea.w, wk[3][3], v);
    v = v > 0.0f ? v : 0.2f * v; p = fmaf(v, at[3], p);
    return p;
}

// ---------------- quad-batched edge pass over dst-sorted edges ---------------------
// R7 structure + end-of-body L1 prefetch of next quad's xl rows (register-neutral).
__global__ __launch_bounds__(256) void edge_q_kernel(const float* __restrict__ We,
                                                     const float* __restrict__ att) {
    __shared__ float sWe[Hh * ED];
    __shared__ float sAtt[Hh];
    int t = threadIdx.x;
    if (t < Hh) {
        sAtt[t] = att[t];
#pragma unroll
        for (int k = 0; k < ED; k++) sWe[t * ED + k] = We[k * Hh + t];
    }
    __syncthreads();

    int lid = t & 31;
    int grp = (blockIdx.x * 8 + (t >> 5)) * 2 + (lid >> 4);
    int sl = lid & 15;
    int h = sl * 4;
    int base = grp * CH;
    if (base >= Ee) return;

    float at[4], wk[4][4];
#pragma unroll
    for (int j = 0; j < 4; j++) {
        at[j] = sAtt[h + j];
#pragma unroll
        for (int k = 0; k < ED; k++) wk[j][k] = sWe[(h + j) * ED + k];
    }

    int cur = -1;
    float4 xr = make_float4(0.f, 0.f, 0.f, 0.f);
    float4 acc = make_float4(0.f, 0.f, 0.f, 0.f);
    float den = 0.0f;

#define FLUSH() do { if (cur >= 0) { \
        float* dp = g_agg + ((long)cur << 6) + h; \
        asm volatile("red.global.add.v4.f32 [%0], {%1, %2, %3, %4};" \
                     :: "l"(dp), "f"(acc.x), "f"(acc.y), "f"(acc.z), "f"(acc.w) : "memory"); \
        if (sl == 0) asm volatile("red.global.add.f32 [%0], %1;" \
                     :: "l"(g_den + cur), "f"(den) : "memory"); } } while (0)
#define PF_L1(p) asm volatile("prefetch.global.L1 [%0];" :: "l"(p))

    int4 p01 = *reinterpret_cast<const int4*>(g_sd + 2 * base);
    int4 p23 = *reinterpret_cast<const int4*>(g_sd + 2 * base + 4);
    PF_L1(g_xl + ((long)p01.x << 6) + h);
    PF_L1(g_xl + ((long)p01.z << 6) + h);
    PF_L1(g_xl + ((long)p23.x << 6) + h);
    PF_L1(g_xl + ((long)p23.z << 6) + h);

#pragma unroll 1
    for (int q = 0; q < CH; q += 4) {
        int e = base + q;
        int s0 = p01.x, d0 = p01.y, s1 = p01.z, d1 = p01.w;
        int s2 = p23.x, d2 = p23.y, s3 = p23.z, d3 = p23.w;
        p01 = *reinterpret_cast<const int4*>(g_sd + 2 * (e + 4));
        p23 = *reinterpret_cast<const int4*>(g_sd + 2 * (e + 4) + 4);

        float4 xl0 = *reinterpret_cast<const float4*>(g_xl + ((long)s0 << 6) + h);
        float4 xl1 = *reinterpret_cast<const float4*>(g_xl + ((long)s1 << 6) + h);
        float4 xl2 = *reinterpret_cast<const float4*>(g_xl + ((long)s2 << 6) + h);
        float4 xl3 = *reinterpret_cast<const float4*>(g_xl + ((long)s3 << 6) + h);
        float4 ea0 = g_eaS[e + 0];
        float4 ea1 = g_eaS[e + 1];
        float4 ea2 = g_eaS[e + 2];
        float4 ea3 = g_eaS[e + 3];

        float4 xr0 = (d0 == cur) ? xr  : *reinterpret_cast<const float4*>(g_xr + ((long)d0 << 6) + h);
        float4 xr1 = (d1 == d0)  ? xr0 : *reinterpret_cast<const float4*>(g_xr + ((long)d1 << 6) + h);
        float4 xr2 = (d2 == d1)  ? xr1 : *reinterpret_cast<const float4*>(g_xr + ((long)d2 << 6) + h);
        float4 xr3 = (d3 == d2)  ? xr2 : *reinterpret_cast<const float4*>(g_xr + ((long)d3 << 6) + h);

        float pp0 = sc4(xl0, xr0, ea0, at, wk);
        float pp1 = sc4(xl1, xr1, ea1, at, wk);
        float pp2 = sc4(xl2, xr2, ea2, at, wk);
        float pp3 = sc4(xl3, xr3, ea3, at, wk);
        pp0 += __shfl_xor_sync(0xffffffffu, pp0, 8);
        pp1 += __shfl_xor_sync(0xffffffffu, pp1, 8);
        pp2 += __shfl_xor_sync(0xffffffffu, pp2, 8);
        pp3 += __shfl_xor_sync(0xffffffffu, pp3, 8);
        pp0 += __shfl_xor_sync(0xffffffffu, pp0, 4);
        pp1 += __shfl_xor_sync(0xffffffffu, pp1, 4);
        pp2 += __shfl_xor_sync(0xffffffffu, pp2, 4);
        pp3 += __shfl_xor_sync(0xffffffffu, pp3, 4);
        pp0 += __shfl_xor_sync(0xffffffffu, pp0, 2);
        pp1 += __shfl_xor_sync(0xffffffffu, pp1, 2);
        pp2 += __shfl_xor_sync(0xffffffffu, pp2, 2);
        pp3 += __shfl_xor_sync(0xffffffffu, pp3, 2);
        pp0 += __shfl_xor_sync(0xffffffffu, pp0, 1);
        pp1 += __shfl_xor_sync(0xffffffffu, pp1, 1);
        pp2 += __shfl_xor_sync(0xffffffffu, pp2, 1);
        pp3 += __shfl_xor_sync(0xffffffffu, pp3, 1);
        float ex0 = __expf(pp0);   // no-max-shift softmax: mathematically identical
        float ex1 = __expf(pp1);
        float ex2 = __expf(pp2);
        float ex3 = __expf(pp3);

        if (d0 != cur) { FLUSH(); cur = d0; acc = make_float4(0.f,0.f,0.f,0.f); den = 0.f; }
        acc.x = fmaf(xl0.x, ex0, acc.x); acc.y = fmaf(xl0.y, ex0, acc.y);
        acc.z = fmaf(xl0.z, ex0, acc.z); acc.w = fmaf(xl0.w, ex0, acc.w);
        den += ex0;
        if (d1 != cur) { FLUSH(); cur = d1; acc = make_float4(0.f,0.f,0.f,0.f); den = 0.f; }
        acc.x = fmaf(xl1.x, ex1, acc.x); acc.y = fmaf(xl1.y, ex1, acc.y);
        acc.z = fmaf(xl1.z, ex1, acc.z); acc.w = fmaf(xl1.w, ex1, acc.w);
        den += ex1;
        if (d2 != cur) { FLUSH(); cur = d2; acc = make_float4(0.f,0.f,0.f,0.f); den = 0.f; }
        acc.x = fmaf(xl2.x, ex2, acc.x); acc.y = fmaf(xl2.y, ex2, acc.y);
        acc.z = fmaf(xl2.z, ex2, acc.z); acc.w = fmaf(xl2.w, ex2, acc.w);
        den += ex2;
        if (d3 != cur) { FLUSH(); cur = d3; acc = make_float4(0.f,0.f,0.f,0.f); den = 0.f; }
        acc.x = fmaf(xl3.x, ex3, acc.x); acc.y = fmaf(xl3.y, ex3, acc.y);
        acc.z = fmaf(xl3.z, ex3, acc.z); acc.w = fmaf(xl3.w, ex3, acc.w);
        den += ex3;
        xr = xr3;   // cur == d3 here

        PF_L1(g_xl + ((long)p01.x << 6) + h);
        PF_L1(g_xl + ((long)p01.z << 6) + h);
        PF_L1(g_xl + ((long)p23.x << 6) + h);
        PF_L1(g_xl + ((long)p23.z << 6) + h);
    }
    FLUSH();
#undef FLUSH
#undef PF_L1
}

// ---------------- proj layer 1: tiled GEMM, elu(layer0) fused into X load ----------
__global__ __launch_bounds__(256) void proj1_gemm_kernel(const float* __restrict__ Wl,
                                                         const float* __restrict__ bl,
                                                         const float* __restrict__ Wr,
                                                         const float* __restrict__ br,
                                                         const float* __restrict__ bias0) {
    __shared__ float sXT[32][68];
    __shared__ float sW[32][128];
    int t = threadIdx.x;
    int m0 = blockIdx.x * 64;
    int tm = t & 15;
    int tn = t >> 4;
    float acc[4][8];
#pragma unroll
    for (int i = 0; i < 4; i++)
#pragma unroll
        for (int j = 0; j < 8; j++) acc[i][j] = 0.0f;

    for (int k0 = 0; k0 < 64; k0 += 32) {
#pragma unroll
        for (int i = 0; i < 8; i++) {
            int idx = t + i * 256;
            int r = idx >> 5;
            int kk = idx & 31;
            int n = m0 + r;
            float v = 0.0f;
            if (n < Nn) {
                float a = g_agg[n * 64 + k0 + kk];
                float vv = a / (g_den[n] + 1e-16f) + bias0[k0 + kk];
                v = vv > 0.0f ? vv : expm1f(vv);
            }
            sXT[kk][r] = v;
        }
#pragma unroll
        for (int i = 0; i < 16; i++) {
            int idx = t + i * 256;
            int kk = idx >> 7;
            int n = idx & 127;
            sW[kk][n] = (n < 64) ? Wl[(k0 + kk) * 64 + n] : Wr[(k0 + kk) * 64 + (n - 64)];
        }
        __syncthreads();
#pragma unroll
        for (int kk = 0; kk < 32; kk++) {
            float4 a = *reinterpret_cast<const float4*>(&sXT[kk][tm * 4]);
            float4 b0 = *reinterpret_cast<const float4*>(&sW[kk][tn * 8]);
            float4 b1 = *reinterpret_cast<const float4*>(&sW[kk][tn * 8 + 4]);
            float av[4] = {a.x, a.y, a.z, a.w};
            float bv[8] = {b0.x, b0.y, b0.z, b0.w, b1.x, b1.y, b1.z, b1.w};
#pragma unroll
            for (int i = 0; i < 4; i++)
#pragma unroll
                for (int j = 0; j < 8; j++)
                    acc[i][j] = fmaf(av[i], bv[j], acc[i][j]);
        }
        __syncthreads();
    }
#pragma unroll
    for (int i = 0; i < 4; i++) {
        int n = m0 + tm * 4 + i;
        if (n >= Nn) break;
#pragma unroll
        for (int j = 0; j < 8; j++) {
            int c = tn * 8 + j;
            if (c < 64) g_xl[n * 64 + c] = acc[i][j] + bl[c];
            else        g_xr[n * 64 + (c - 64)] = acc[i][j] + br[c - 64];
        }
    }
#pragma unroll
    for (int i = 0; i < 16; i++) {
        int idx = t + i * 256;
        int n = m0 + (idx >> 6);
        if (n < Nn) g_agg[n * 64 + (idx & 63)] = 0.0f;
    }
    if (t < 64 && m0 + t < Nn) g_den[m0 + t] = 0.0f;
}

// ---------------- segmented pool (batch sorted): elu fused -------------------------
__global__ __launch_bounds__(256) void pool_kernel(const int* __restrict__ batch,
                                                   const float* __restrict__ bias1) {
    int t = threadIdx.x;
    int h = t & 63;
    int c = t >> 6;
    int n0 = blockIdx.x * 64 + c * 16;
    float b1 = bias1[h];
    int cur = -1;
    float acc = 0.0f, cnt = 0.0f;
#pragma unroll 1
    for (int k = 0; k < 16; k++) {
        int n = n0 + k;
        if (n >= Nn) break;
        int b = batch[n];
        if (b != cur) {
            if (cur >= 0) {
                atomicAdd(&g_pool[cur * Hh + h], acc);
                if (h == 0) atomicAdd(&g_cnt[cur], cnt);
            }
            cur = b; acc = 0.0f; cnt = 0.0f;
        }
        float v = g_agg[n * 64 + h] / (g_den[n] + 1e-16f) + b1;
        v = v > 0.0f ? v : expm1f(v);
        acc += v; cnt += 1.0f;
    }
    if (cur >= 0) {
        atomicAdd(&g_pool[cur * Hh + h], acc);
        if (h == 0) atomicAdd(&g_cnt[cur], cnt);
    }
}

// ---------------- head (also re-zeroes g_cur for the NEXT call) --------------------
__global__ __launch_bounds__(FCH) void head_kernel(const float* __restrict__ fc1w,
                                                   const float* __restrict__ fc1b,
                                                   const float* __restrict__ fc2w,
                                                   const float* __restrict__ fc2b,
                                                   float* __restrict__ out) {
    __shared__ float sg[Hh];
    __shared__ float sfc[FCH];
    __shared__ float slog[NC];
    int g = blockIdx.x;
    int t = threadIdx.x;
    for (int i = g * FCH + t; i < Nn; i += Gg * FCH) g_cur[i] = 0;
    if (t < Hh) {
        float inv = 1.0f / fmaxf(g_cnt[g], 1.0f);
        sg[t] = g_pool[g * Hh + t] * inv;
    }
    __syncthreads();
    float a = fc1b[t];
#pragma unroll 8
    for (int k = 0; k < Hh; k++) a = fmaf(sg[k], fc1w[k * FCH + t], a);
    sfc[t] = fmaxf(a, 0.0f);
    __syncthreads();
    if (t < NC) {
        float z = fc2b[t];
#pragma unroll 8
        for (int k = 0; k < FCH; k++) z = fmaf(sfc[k], fc2w[k * NC + t], z);
        slog[t] = z;
    }
    __syncthreads();
    if (t == 0) {
        float l0 = slog[0], l1 = slog[1];
        float m = fmaxf(l0, l1);
        float lse = m + logf(expf(l0 - m) + expf(l1 - m));
        out[g * NC + 0] = l0 - lse;
        out[g * NC + 1] = l1 - lse;
    }
}

// -----------------------------------------------------------------------------------
extern "C" void kernel_launch(void* const* d_in, const int* in_sizes, int n_in,
                              void* d_out, int out_size) {
    const float* x      = (const float*)d_in[0];
    const int*   ei     = (const int*)d_in[1];
    const float* ea     = (const float*)d_in[2];
    const int*   batch  = (const int*)d_in[3];
    const float* Wl0    = (const float*)d_in[4];
    const float* bl0    = (const float*)d_in[5];
    const float* Wr0    = (const float*)d_in[6];
    const float* br0    = (const float*)d_in[7];
    const float* We0    = (const float*)d_in[8];
    const float* att0   = (const float*)d_in[9];
    const float* bias0  = (const float*)d_in[10];
    const float* Wl1    = (const float*)d_in[11];
    const float* bl1    = (const float*)d_in[12];
    const float* Wr1    = (const float*)d_in[13];
    const float* br1    = (const float*)d_in[14];
    const float* We1    = (const float*)d_in[15];
    const float* att1   = (const float*)d_in[16];
    const float* bias1  = (const float*)d_in[17];
    const float* fc1w   = (const float*)d_in[18];
    const float* fc1b   = (const float*)d_in[19];
    const float* fc2w   = (const float*)d_in[20];
    const float* fc2b   = (const float*)d_in[21];
    float* out = (float*)d_out;

    const int egrid = (Ee / CH + 15) / 16;                   // 1563
    const int mgrid = (Nn + 63) / 64;                        // 782

    hist_kernel<<<FB, 256>>>(ei);                               // histogram + ranks
    scanA_kernel<<<SB, 256>>>();
    scanB_kernel<<<1, 256>>>();
    scanC_kernel<<<SB, 256>>>();
    scatproj_kernel<<<FB, 256>>>(ei, ea, x, Wl0, bl0, Wr0, br0);  // scatter + proj0 fused
    edge_q_kernel<<<egrid, 256>>>(We0, att0);
    proj1_gemm_kernel<<<mgrid, 256>>>(Wl1, bl1, Wr1, br1, bias0);
    edge_q_kernel<<<egrid, 256>>>(We1, att1);
    pool_kernel<<<mgrid, 256>>>(batch, bias1);
    head_kernel<<<Gg, FCH>>>(fc1w, fc1b, fc2w, fc2b, out);      // + re-zero g_cur
}

// round 16
// speedup vs baseline: 1.0330x; 1.0330x over previous
#include <cuda_runtime.h>
#include <cuda_bf16.h>
#include <cstdint>

#define Nn 50000
#define Ee 1600000
#define Hh 64
#define INC 7
#define ED 4
#define Gg 256
#define FCH 128
#define NC 2
#define CH 64                      // edges per 16-lane group (Ee % CH == 0)
#define QB 1563                    // hist blocks fused into proj0 (QB*256*4 >= Ee)
#define SB 196                     // scan blocks (SB*256 >= Nn)

// ---------------- device scratch ----------------------------------------------------
__device__ __align__(16) float g_xl[Nn * Hh];
__device__ __align__(16) float g_xr[Nn * Hh];
__device__ __align__(16) float g_agg[Nn * Hh];
__device__ float g_den[Nn];
__device__ float g_pool[Gg * Hh];
__device__ float g_cnt[Gg];
__device__ int   g_cur[Nn];                    // zero-init; re-zeroed by head_kernel
__device__ int   g_off[Nn + 1];
__device__ int   g_bsum[SB];
__device__ __align__(16) int    g_sd[2 * Ee + 16];   // (src,dst) pairs, dst-sorted (+pad)
__device__ __align__(16) float4 g_eaS[Ee];           // edge_attr permuted to sorted order

// ---------------- proj layer 0 (in=7) + zero agg/den; fused dst histogram ----------
__global__ void proj0_kernel(const float* __restrict__ x,
                             const float* __restrict__ Wl, const float* __restrict__ bl,
                             const float* __restrict__ Wr, const float* __restrict__ br,
                             const int* __restrict__ ei) {
    int t = threadIdx.x;
    // fused histogram (g_cur pre-zeroed by previous call's head_kernel / static init)
    if (blockIdx.x < QB) {
        int i = (blockIdx.x * 256 + t) * 4;
        if (i < Ee) {
            int4 d = *reinterpret_cast<const int4*>(ei + Ee + i);
            atomicAdd(&g_cur[d.x], 1);
            atomicAdd(&g_cur[d.y], 1);
            atomicAdd(&g_cur[d.z], 1);
            atomicAdd(&g_cur[d.w], 1);
        }
    }
    int idx = blockIdx.x * blockDim.x + t;
    if (idx >= Nn * Hh) return;
    int n = idx >> 6;
    int h = idx & 63;
    const float* xrow = x + n * INC;
    float al = bl[h];
    float ar = br[h];
#pragma unroll
    for (int k = 0; k < INC; k++) {
        float xv = xrow[k];
        al = fmaf(xv, Wl[k * Hh + h], al);
        ar = fmaf(xv, Wr[k * Hh + h], ar);
    }
    g_xl[idx] = al;
    g_xr[idx] = ar;
    g_agg[idx] = 0.0f;
    if (h == 0) g_den[n] = 0.0f;
}

// ---------------- parallel scan stages ---------------------------------------------
__global__ __launch_bounds__(256) void scanA_kernel() {
    __shared__ int sp[256];
    int t = threadIdx.x;
    int i = blockIdx.x * 256 + t;
    int v = (i < Nn) ? g_cur[i] : 0;
    sp[t] = v;
    __syncthreads();
#pragma unroll
    for (int off = 128; off > 0; off >>= 1) {
        if (t < off) sp[t] += sp[t + off];
        __syncthreads();
    }
    if (t == 0) g_bsum[blockIdx.x] = sp[0];
}

__global__ __launch_bounds__(256) void scanB_kernel() {
    __shared__ int sp[256];
    int t = threadIdx.x;
    int v = (t < SB) ? g_bsum[t] : 0;
    sp[t] = v;
    __syncthreads();
#pragma unroll
    for (int off = 1; off < 256; off <<= 1) {
        int u = (t >= off) ? sp[t - off] : 0;
        __syncthreads();
        sp[t] += u;
        __syncthreads();
    }
    if (t < SB) g_bsum[t] = sp[t] - v;   // exclusive
    for (int i = t; i < Gg * Hh; i += 256) g_pool[i] = 0.0f;
    if (t < Gg) g_cnt[t] = 0.0f;
}

__global__ __launch_bounds__(256) void scanC_kernel() {
    __shared__ int sp[256];
    int t = threadIdx.x;
    int i = blockIdx.x * 256 + t;
    int v = (i < Nn) ? g_cur[i] : 0;
    sp[t] = v;
    __syncthreads();
#pragma unroll
    for (int off = 1; off < 256; off <<= 1) {
        int u = (t >= off) ? sp[t - off] : 0;
        __syncthreads();
        sp[t] += u;
        __syncthreads();
    }
    if (i < Nn) {
        int off = g_bsum[blockIdx.x] + sp[t] - v;
        g_off[i] = off;
        g_cur[i] = off;
    }
    if (i == Nn - 1) g_off[Nn] = Ee;
}

// ---------------- counting sort: scatter (unroll 8) --------------------------------
__global__ void scatter_kernel(const int* __restrict__ ei, const float* __restrict__ ea) {
    int i = (blockIdx.x * blockDim.x + threadIdx.x) * 8;
    if (i >= Ee) return;
    int4 sa = *reinterpret_cast<const int4*>(ei + i);
    int4 sb = *reinterpret_cast<const int4*>(ei + i + 4);
    int4 da = *reinterpret_cast<const int4*>(ei + Ee + i);
    int4 db = *reinterpret_cast<const int4*>(ei + Ee + i + 4);
    int ss[8] = {sa.x, sa.y, sa.z, sa.w, sb.x, sb.y, sb.z, sb.w};
    int dd[8] = {da.x, da.y, da.z, da.w, db.x, db.y, db.z, db.w};
    float4 ev[8];
#pragma unroll
    for (int k = 0; k < 8; k++) ev[k] = *reinterpret_cast<const float4*>(ea + 4 * (i + k));
    int pp[8];
#pragma unroll
    for (int k = 0; k < 8; k++) pp[k] = atomicAdd(&g_cur[dd[k]], 1);
#pragma unroll
    for (int k = 0; k < 8; k++) {
        *reinterpret_cast<int2*>(g_sd + 2 * pp[k]) = make_int2(ss[k], dd[k]);
        g_eaS[pp[k]] = ev[k];
    }
}

// ---------------- per-edge score helper --------------------------------------------
__device__ __forceinline__ float sc4(float4 xl, float4 xr, float4 ea,
                                     const float* at, const float (*wk)[4]) {
    float p = 0.0f, v;
    v = xl.x + xr.x;
    v = fmaf(ea.x, wk[0][0], v); v = fmaf(ea.y, wk[0][1], v);
    v = fmaf(ea.z, wk[0][2], v); v = fmaf(ea.w, wk[0][3], v);
    v = v > 0.0f ? v : 0.2f * v; p = fmaf(v, at[0], p);
    v = xl.y + xr.y;
    v = fmaf(ea.x, wk[1][0], v); v = fmaf(ea.y, wk[1][1], v);
    v = fmaf(ea.z, wk[1][2], v); v = fmaf(ea.w, wk[1][3], v);
    v = v > 0.0f ? v : 0.2f * v; p = fmaf(v, at[1], p);
    v = xl.z + xr.z;
    v = fmaf(ea.x, wk[2][0], v); v = fmaf(ea.y, wk[2][1], v);
    v = fmaf(ea.z, wk[2][2], v); v = fmaf(ea.w, wk[2][3], v);
    v = v > 0.0f ? v : 0.2f * v; p = fmaf(v, at[2], p);
    v = xl.w + xr.w;
    v = fmaf(ea.x, wk[3][0], v); v = fmaf(ea.y, wk[3][1], v);
    v = fmaf(ea.z, wk[3][2], v); v = fmaf(ea.w, wk[3][3], v);
    v = v > 0.0f ? v : 0.2f * v; p = fmaf(v, at[3], p);
    return p;
}

// ---------------- quad-batched edge pass over dst-sorted edges (R7 config) ---------
__global__ __launch_bounds__(256) void edge_q_kernel(const float* __restrict__ We,
                                                     const float* __restrict__ att) {
    __shared__ float sWe[Hh * ED];
    __shared__ float sAtt[Hh];
    int t = threadIdx.x;
    if (t < Hh) {
        sAtt[t] = att[t];
#pragma unroll
        for (int k = 0; k < ED; k++) sWe[t * ED + k] = We[k * Hh + t];
    }
    __syncthreads();

    int lid = t & 31;
    int grp = (blockIdx.x * 8 + (t >> 5)) * 2 + (lid >> 4);
    int sl = lid & 15;
    int h = sl * 4;
    int base = grp * CH;
    if (base >= Ee) return;

    float at[4], wk[4][4];
#pragma unroll
    for (int j = 0; j < 4; j++) {
        at[j] = sAtt[h + j];
#pragma unroll
        for (int k = 0; k < ED; k++) wk[j][k] = sWe[(h + j) * ED + k];
    }

    int cur = -1;
    float4 xr = make_float4(0.f, 0.f, 0.f, 0.f);
    float4 acc = make_float4(0.f, 0.f, 0.f, 0.f);
    float den = 0.0f;

#define FLUSH() do { if (cur >= 0) { \
        float* dp = g_agg + ((long)cur << 6) + h; \
        asm volatile("red.global.add.v4.f32 [%0], {%1, %2, %3, %4};" \
                     :: "l"(dp), "f"(acc.x), "f"(acc.y), "f"(acc.z), "f"(acc.w) : "memory"); \
        if (sl == 0) asm volatile("red.global.add.f32 [%0], %1;" \
                     :: "l"(g_den + cur), "f"(den) : "memory"); } } while (0)

    int4 p01 = *reinterpret_cast<const int4*>(g_sd + 2 * base);
    int4 p23 = *reinterpret_cast<const int4*>(g_sd + 2 * base + 4);

#pragma unroll 1
    for (int q = 0; q < CH; q += 4) {
        int e = base + q;
        int s0 = p01.x, d0 = p01.y, s1 = p01.z, d1 = p01.w;
        int s2 = p23.x, d2 = p23.y, s3 = p23.z, d3 = p23.w;
        p01 = *reinterpret_cast<const int4*>(g_sd + 2 * (e + 4));
        p23 = *reinterpret_cast<const int4*>(g_sd + 2 * (e + 4) + 4);

        float4 xl0 = *reinterpret_cast<const float4*>(g_xl + ((long)s0 << 6) + h);
        float4 xl1 = *reinterpret_cast<const float4*>(g_xl + ((long)s1 << 6) + h);
        float4 xl2 = *reinterpret_cast<const float4*>(g_xl + ((long)s2 << 6) + h);
        float4 xl3 = *reinterpret_cast<const float4*>(g_xl + ((long)s3 << 6) + h);
        float4 ea0 = g_eaS[e + 0];
        float4 ea1 = g_eaS[e + 1];
        float4 ea2 = g_eaS[e + 2];
        float4 ea3 = g_eaS[e + 3];

        float4 xr0 = (d0 == cur) ? xr  : *reinterpret_cast<const float4*>(g_xr + ((long)d0 << 6) + h);
        float4 xr1 = (d1 == d0)  ? xr0 : *reinterpret_cast<const float4*>(g_xr + ((long)d1 << 6) + h);
        float4 xr2 = (d2 == d1)  ? xr1 : *reinterpret_cast<const float4*>(g_xr + ((long)d2 << 6) + h);
        float4 xr3 = (d3 == d2)  ? xr2 : *reinterpret_cast<const float4*>(g_xr + ((long)d3 << 6) + h);

        float pp0 = sc4(xl0, xr0, ea0, at, wk);
        float pp1 = sc4(xl1, xr1, ea1, at, wk);
        float pp2 = sc4(xl2, xr2, ea2, at, wk);
        float pp3 = sc4(xl3, xr3, ea3, at, wk);
        pp0 += __shfl_xor_sync(0xffffffffu, pp0, 8);
        pp1 += __shfl_xor_sync(0xffffffffu, pp1, 8);
        pp2 += __shfl_xor_sync(0xffffffffu, pp2, 8);
        pp3 += __shfl_xor_sync(0xffffffffu, pp3, 8);
        pp0 += __shfl_xor_sync(0xffffffffu, pp0, 4);
        pp1 += __shfl_xor_sync(0xffffffffu, pp1, 4);
        pp2 += __shfl_xor_sync(0xffffffffu, pp2, 4);
        pp3 += __shfl_xor_sync(0xffffffffu, pp3, 4);
        pp0 += __shfl_xor_sync(0xffffffffu, pp0, 2);
        pp1 += __shfl_xor_sync(0xffffffffu, pp1, 2);
        pp2 += __shfl_xor_sync(0xffffffffu, pp2, 2);
        pp3 += __shfl_xor_sync(0xffffffffu, pp3, 2);
        pp0 += __shfl_xor_sync(0xffffffffu, pp0, 1);
        pp1 += __shfl_xor_sync(0xffffffffu, pp1, 1);
        pp2 += __shfl_xor_sync(0xffffffffu, pp2, 1);
        pp3 += __shfl_xor_sync(0xffffffffu, pp3, 1);
        float ex0 = __expf(pp0);   // no-max-shift softmax: mathematically identical
        float ex1 = __expf(pp1);
        float ex2 = __expf(pp2);
        float ex3 = __expf(pp3);

        if (d0 != cur) { FLUSH(); cur = d0; acc = make_float4(0.f,0.f,0.f,0.f); den = 0.f; }
        acc.x = fmaf(xl0.x, ex0, acc.x); acc.y = fmaf(xl0.y, ex0, acc.y);
        acc.z = fmaf(xl0.z, ex0, acc.z); acc.w = fmaf(xl0.w, ex0, acc.w);
        den += ex0;
        if (d1 != cur) { FLUSH(); cur = d1; acc = make_float4(0.f,0.f,0.f,0.f); den = 0.f; }
        acc.x = fmaf(xl1.x, ex1, acc.x); acc.y = fmaf(xl1.y, ex1, acc.y);
        acc.z = fmaf(xl1.z, ex1, acc.z); acc.w = fmaf(xl1.w, ex1, acc.w);
        den += ex1;
        if (d2 != cur) { FLUSH(); cur = d2; acc = make_float4(0.f,0.f,0.f,0.f); den = 0.f; }
        acc.x = fmaf(xl2.x, ex2, acc.x); acc.y = fmaf(xl2.y, ex2, acc.y);
        acc.z = fmaf(xl2.z, ex2, acc.z); acc.w = fmaf(xl2.w, ex2, acc.w);
        den += ex2;
        if (d3 != cur) { FLUSH(); cur = d3; acc = make_float4(0.f,0.f,0.f,0.f); den = 0.f; }
        acc.x = fmaf(xl3.x, ex3, acc.x); acc.y = fmaf(xl3.y, ex3, acc.y);
        acc.z = fmaf(xl3.z, ex3, acc.z); acc.w = fmaf(xl3.w, ex3, acc.w);
        den += ex3;
        xr = xr3;   // cur == d3 here
    }
    FLUSH();
#undef FLUSH
}

// ---------------- proj layer 1: tiled GEMM, elu(layer0) fused into X load ----------
__global__ __launch_bounds__(256) void proj1_gemm_kernel(const float* __restrict__ Wl,
                                                         const float* __restrict__ bl,
                                                         const float* __restrict__ Wr,
                                                         const float* __restrict__ br,
                                                         const float* __restrict__ bias0) {
    __shared__ float sXT[32][68];
    __shared__ float sW[32][128];
    int t = threadIdx.x;
    int m0 = blockIdx.x * 64;
    int tm = t & 15;
    int tn = t >> 4;
    float acc[4][8];
#pragma unroll
    for (int i = 0; i < 4; i++)
#pragma unroll
        for (int j = 0; j < 8; j++) acc[i][j] = 0.0f;

    for (int k0 = 0; k0 < 64; k0 += 32) {
#pragma unroll
        for (int i = 0; i < 8; i++) {
            int idx = t + i * 256;
            int r = idx >> 5;
            int kk = idx & 31;
            int n = m0 + r;
            float v = 0.0f;
            if (n < Nn) {
                float a = g_agg[n * 64 + k0 + kk];
                float vv = a / (g_den[n] + 1e-16f) + bias0[k0 + kk];
                v = vv > 0.0f ? vv : expm1f(vv);
            }
            sXT[kk][r] = v;
        }
#pragma unroll
        for (int i = 0; i < 16; i++) {
            int idx = t + i * 256;
            int kk = idx >> 7;
            int n = idx & 127;
            sW[kk][n] = (n < 64) ? Wl[(k0 + kk) * 64 + n] : Wr[(k0 + kk) * 64 + (n - 64)];
        }
        __syncthreads();
#pragma unroll
        for (int kk = 0; kk < 32; kk++) {
            float4 a = *reinterpret_cast<const float4*>(&sXT[kk][tm * 4]);
            float4 b0 = *reinterpret_cast<const float4*>(&sW[kk][tn * 8]);
            float4 b1 = *reinterpret_cast<const float4*>(&sW[kk][tn * 8 + 4]);
            float av[4] = {a.x, a.y, a.z, a.w};
            float bv[8] = {b0.x, b0.y, b0.z, b0.w, b1.x, b1.y, b1.z, b1.w};
#pragma unroll
            for (int i = 0; i < 4; i++)
#pragma unroll
                for (int j = 0; j < 8; j++)
                    acc[i][j] = fmaf(av[i], bv[j], acc[i][j]);
        }
        __syncthreads();
    }
#pragma unroll
    for (int i = 0; i < 4; i++) {
        int n = m0 + tm * 4 + i;
        if (n >= Nn) break;
#pragma unroll
        for (int j = 0; j < 8; j++) {
            int c = tn * 8 + j;
            if (c < 64) g_xl[n * 64 + c] = acc[i][j] + bl[c];
            else        g_xr[n * 64 + (c - 64)] = acc[i][j] + br[c - 64];
        }
    }
    // zero accumulators for layer 1 (this block owns rows m0..m0+63)
#pragma unroll
    for (int i = 0; i < 16; i++) {
        int idx = t + i * 256;
        int r = idx >> 6;
        int k = idx & 63;
        int n = m0 + r;
        if (n < Nn) g_agg[n * 64 + k] = 0.0f;
    }
    if (t < 64 && m0 + t < Nn) g_den[m0 + t] = 0.0f;
}

// ---------------- segmented pool (batch sorted): elu fused -------------------------
__global__ __launch_bounds__(256) void pool_kernel(const int* __restrict__ batch,
                                                   const float* __restrict__ bias1) {
    int t = threadIdx.x;
    int h = t & 63;
    int c = t >> 6;
    int n0 = blockIdx.x * 64 + c * 16;
    float b1 = bias1[h];
    int cur = -1;
    float acc = 0.0f, cnt = 0.0f;
#pragma unroll 1
    for (int k = 0; k < 16; k++) {
        int n = n0 + k;
        if (n >= Nn) break;
        int b = batch[n];
        if (b != cur) {
            if (cur >= 0) {
                atomicAdd(&g_pool[cur * Hh + h], acc);
                if (h == 0) atomicAdd(&g_cnt[cur], cnt);
            }
            cur = b; acc = 0.0f; cnt = 0.0f;
        }
        float v = g_agg[n * 64 + h] / (g_den[n] + 1e-16f) + b1;
        v = v > 0.0f ? v : expm1f(v);
        acc += v; cnt += 1.0f;
    }
    if (cur >= 0) {
        atomicAdd(&g_pool[cur * Hh + h], acc);
        if (h == 0) atomicAdd(&g_cnt[cur], cnt);
    }
}

// ---------------- head (also re-zeroes g_cur for the NEXT call) --------------------
__global__ __launch_bounds__(FCH) void head_kernel(const float* __restrict__ fc1w,
                                                   const float* __restrict__ fc1b,
                                                   const float* __restrict__ fc2w,
                                                   const float* __restrict__ fc2b,
                                                   float* __restrict__ out) {
    __shared__ float sg[Hh];
    __shared__ float sfc[FCH];
    __shared__ float slog[NC];
    int g = blockIdx.x;
    int t = threadIdx.x;
    // re-zero histogram buffer for next call (first call: static zero-init)
    for (int i = g * FCH + t; i < Nn; i += Gg * FCH) g_cur[i] = 0;
    if (t < Hh) {
        float inv = 1.0f / fmaxf(g_cnt[g], 1.0f);
        sg[t] = g_pool[g * Hh + t] * inv;
    }
    __syncthreads();
    float a = fc1b[t];
#pragma unroll 8
    for (int k = 0; k < Hh; k++) a = fmaf(sg[k], fc1w[k * FCH + t], a);
    sfc[t] = fmaxf(a, 0.0f);
    __syncthreads();
    if (t < NC) {
        float z = fc2b[t];
#pragma unroll 8
        for (int k = 0; k < FCH; k++) z = fmaf(sfc[k], fc2w[k * NC + t], z);
        slog[t] = z;
    }
    __syncthreads();
    if (t == 0) {
        float l0 = slog[0], l1 = slog[1];
        float m = fmaxf(l0, l1);
        float lse = m + logf(expf(l0 - m) + expf(l1 - m));
        out[g * NC + 0] = l0 - lse;
        out[g * NC + 1] = l1 - lse;
    }
}

// -----------------------------------------------------------------------------------
extern "C" void kernel_launch(void* const* d_in, const int* in_sizes, int n_in,
                              void* d_out, int out_size) {
    const float* x      = (const float*)d_in[0];
    const int*   ei     = (const int*)d_in[1];
    const float* ea     = (const float*)d_in[2];
    const int*   batch  = (const int*)d_in[3];
    const float* Wl0    = (const float*)d_in[4];
    const float* bl0    = (const float*)d_in[5];
    const float* Wr0    = (const float*)d_in[6];
    const float* br0    = (const float*)d_in[7];
    const float* We0    = (const float*)d_in[8];
    const float* att0   = (const float*)d_in[9];
    const float* bias0  = (const float*)d_in[10];
    const float* Wl1    = (const float*)d_in[11];
    const float* bl1    = (const float*)d_in[12];
    const float* Wr1    = (const float*)d_in[13];
    const float* br1    = (const float*)d_in[14];
    const float* We1    = (const float*)d_in[15];
    const float* att1   = (const float*)d_in[16];
    const float* bias1  = (const float*)d_in[17];
    const float* fc1w   = (const float*)d_in[18];
    const float* fc1b   = (const float*)d_in[19];
    const float* fc2w   = (const float*)d_in[20];
    const float* fc2b   = (const float*)d_in[21];
    float* out = (float*)d_out;

    const int pgrid = (Nn * Hh + 255) / 256;                 // 12500
    const int sgrid = (Ee / 8 + 255) / 256;                  // 782
    const int egrid = (Ee / CH + 15) / 16;                   // 1563
    const int mgrid = (Nn + 63) / 64;                        // 782

    proj0_kernel<<<pgrid, 256>>>(x, Wl0, bl0, Wr0, br0, ei);   // + fused histogram
    scanA_kernel<<<SB, 256>>>();
    scanB_kernel<<<1, 256>>>();
    scanC_kernel<<<SB, 256>>>();
    scatter_kernel<<<sgrid, 256>>>(ei, ea);
    edge_q_kernel<<<egrid, 256>>>(We0, att0);
    proj1_gemm_kernel<<<mgrid, 256>>>(Wl1, bl1, Wr1, br1, bias0);
    edge_q_kernel<<<egrid, 256>>>(We1, att1);
    pool_kernel<<<mgrid, 256>>>(batch, bias1);
    head_kernel<<<Gg, FCH>>>(fc1w, fc1b, fc2w, fc2b, out);     // + re-zero g_cur
}